// round 1
// baseline (speedup 1.0000x reference)
#include <cuda_runtime.h>

// Problem constants (fixed by reference)
#define BB   4
#define NN   100000
#define KK   16
#define DD   6
#define FF   13
#define LL   3
#define PTS  (BB * NN)          // 400000 points
#define SLOPE 0.2f
#define EPSN  1e-5f

typedef unsigned long long u64;

// ---- f32x2 packed helpers (sm_103a) ----
__device__ __forceinline__ u64 pk2(float lo, float hi) {
    u64 r;
    asm("mov.b64 %0, {%1, %2};" : "=l"(r) : "f"(lo), "f"(hi));
    return r;
}
__device__ __forceinline__ void up2(u64 v, float& lo, float& hi) {
    asm("mov.b64 {%0, %1}, %2;" : "=f"(lo), "=f"(hi) : "l"(v));
}
__device__ __forceinline__ u64 ffma2(u64 a, u64 b, u64 c) {
    u64 d;
    asm("fma.rn.f32x2 %0, %1, %2, %3;" : "=l"(d) : "l"(a), "l"(b), "l"(c));
    return d;
}

__device__ __forceinline__ float leaky(float x) {
    return fmaxf(x, 0.0f) + SLOPE * fminf(x, 0.0f);
}

__global__ void __launch_bounds__(256)
atom_emb_mp_kernel(const float* __restrict__ dist,
                   const float* __restrict__ atomtypes,
                   const float* __restrict__ w1g,
                   const float* __restrict__ b1g,
                   const float* __restrict__ w2g,
                   const float* __restrict__ b2g,
                   const float* __restrict__ gnw,
                   const float* __restrict__ gnb,
                   float* __restrict__ out)
{
    // Packed (w,w) weights in SMEM: one LDS.64 broadcast feeds one FFMA2.
    __shared__ u64  sw1[LL * FF * FF];   // 507 * 8 B
    __shared__ u64  sb1[LL * FF];        // 39  * 8 B
    __shared__ u64  sw2[LL * FF * DD];   // 234 * 8 B
    __shared__ float sb2[LL * DD];
    __shared__ float sgw[LL * DD];
    __shared__ float sgb[LL * DD];

    for (int i = threadIdx.x; i < LL * FF * FF; i += blockDim.x) {
        float w = w1g[i]; sw1[i] = pk2(w, w);
    }
    for (int i = threadIdx.x; i < LL * FF; i += blockDim.x) {
        float w = b1g[i]; sb1[i] = pk2(w, w);
    }
    for (int i = threadIdx.x; i < LL * FF * DD; i += blockDim.x) {
        float w = w2g[i]; sw2[i] = pk2(w, w);
    }
    for (int i = threadIdx.x; i < LL * DD; i += blockDim.x) {
        sb2[i] = b2g[i];
        sgw[i] = gnw[i];
        sgb[i] = gnb[i];
    }
    __syncthreads();

    const int p = blockIdx.x * blockDim.x + threadIdx.x;
    if (p < PTS) {
        const float* atb = atomtypes + (size_t)p * (KK * DD);  // 96 floats, 16B-aligned
        const float* dsb = dist      + (size_t)p * KK;          // 16 floats

        float pe[DD];
        #pragma unroll
        for (int j = 0; j < DD; ++j) pe[j] = 1.0f;

        #pragma unroll 1
        for (int l = 0; l < LL; ++l) {
            const u64* w1l = sw1 + l * FF * FF;
            const u64* b1l = sb1 + l * FF;
            const u64* w2l = sw2 + l * FF * DD;

            u64 pep[DD];
            #pragma unroll
            for (int j = 0; j < DD; ++j) pep[j] = pk2(pe[j], pe[j]);

            u64 acc[DD];
            #pragma unroll
            for (int j = 0; j < DD; ++j) acc[j] = 0ull;   // (0.0f, 0.0f)

            // 8 packed k-pairs: lanes (lo,hi) = neighbors (2*kp, 2*kp+1)
            #pragma unroll 1
            for (int kp = 0; kp < KK / 2; ++kp) {
                const float4* ap = (const float4*)(atb + kp * 12);
                const float4 a0 = ap[0];   // k0[0..3]
                const float4 a1 = ap[1];   // k0[4..5], k1[0..1]
                const float4 a2 = ap[2];   // k1[2..5]
                const float2 dd = *(const float2*)(dsb + kp * 2);

                u64 feat[FF];
                #pragma unroll
                for (int j = 0; j < DD; ++j) feat[j] = pep[j];
                feat[6]  = pk2(a0.x, a1.z);
                feat[7]  = pk2(a0.y, a1.w);
                feat[8]  = pk2(a0.z, a2.x);
                feat[9]  = pk2(a0.w, a2.y);
                feat[10] = pk2(a1.x, a2.z);
                feat[11] = pk2(a1.y, a2.w);
                feat[12] = pk2(dd.x, dd.y);

                // h = leaky(feat @ W1 + b1)   (169 FFMA2)
                u64 h[FF];
                #pragma unroll
                for (int j = 0; j < FF; ++j) h[j] = b1l[j];
                #pragma unroll
                for (int i = 0; i < FF; ++i) {
                    const u64 f = feat[i];
                    #pragma unroll
                    for (int j = 0; j < FF; ++j)
                        h[j] = ffma2(f, w1l[i * FF + j], h[j]);
                }
                #pragma unroll
                for (int j = 0; j < FF; ++j) {
                    float x, y;
                    up2(h[j], x, y);
                    h[j] = pk2(leaky(x), leaky(y));
                }

                // acc += h @ W2               (78 FFMA2)
                #pragma unroll
                for (int i = 0; i < FF; ++i) {
                    const u64 hh = h[i];
                    #pragma unroll
                    for (int j = 0; j < DD; ++j)
                        acc[j] = ffma2(hh, w2l[i * DD + j], acc[j]);
                }
            }

            // reduce the two packed lanes; b2 was added once per k in the ref
            float msg[DD];
            #pragma unroll
            for (int j = 0; j < DD; ++j) {
                float x, y;
                up2(acc[j], x, y);
                msg[j] = x + y + (float)KK * sb2[l * DD + j];
            }

            // GroupNorm(2 groups of 3) + leaky + residual
            #pragma unroll
            for (int g = 0; g < 2; ++g) {
                const float m0 = msg[3 * g + 0];
                const float m1 = msg[3 * g + 1];
                const float m2 = msg[3 * g + 2];
                const float mu = (m0 + m1 + m2) * (1.0f / 3.0f);
                const float d0 = m0 - mu, d1 = m1 - mu, d2 = m2 - mu;
                const float var = (d0 * d0 + d1 * d1 + d2 * d2) * (1.0f / 3.0f);
                const float inv = rsqrtf(var + EPSN);
                const float dv[3] = {d0, d1, d2};
                #pragma unroll
                for (int c = 0; c < 3; ++c) {
                    const int ch = 3 * g + c;
                    const float v = dv[c] * inv * sgw[l * DD + ch] + sgb[l * DD + ch];
                    pe[ch] += leaky(v);
                }
            }
        }

        // point_emb out: 6 floats per point, 8B-aligned -> 3x STG.64
        float2* o = (float2*)(out + (size_t)p * DD);
        o[0] = make_float2(pe[0], pe[1]);
        o[1] = make_float2(pe[2], pe[3]);
        o[2] = make_float2(pe[4], pe[5]);
    }
}

extern "C" void kernel_launch(void* const* d_in, const int* in_sizes, int n_in,
                              void* d_out, int out_size)
{
    const float* dist      = (const float*)d_in[0];
    const float* atomtypes = (const float*)d_in[1];
    const float* w1        = (const float*)d_in[2];
    const float* b1        = (const float*)d_in[3];
    const float* w2        = (const float*)d_in[4];
    const float* b2        = (const float*)d_in[5];
    const float* gnw       = (const float*)d_in[6];
    const float* gnb       = (const float*)d_in[7];
    float* out             = (float*)d_out;

    const int threads = 256;
    const int blocks  = (PTS + threads - 1) / threads;
    atom_emb_mp_kernel<<<blocks, threads>>>(dist, atomtypes, w1, b1, w2, b2,
                                            gnw, gnb, out);
}